// round 3
// baseline (speedup 1.0000x reference)
#include <cuda_runtime.h>
#include <math.h>

// ---------------- problem constants ----------------
#define NANCH   120000
#define KPRE    2000
#define KPOST   512
#define IMG     800.0f
#define SCALE   0.25f
#define CLIPC   4.135166556742356f
#define HF      200
#define WF      200
#define CF      256
#define HW      (HF*WF)          // 40000
#define NWORD   32
#define NPAD    2048
#define PT      625              // p-tiles of 64 (HW/64)
#define CT      4                // c-tiles of 64 (CF/64)
#define TTOT    (PT*CT)          // 2500 transpose tiles
#define THALF   1250

// ---------------- device scratch ----------------
__device__ float               g_boxes[NANCH * 4];
__device__ unsigned int        g_hist[65536];
__device__ unsigned int        g_hist2[65536];
__device__ int                 g_T16;
__device__ unsigned int        g_S;
__device__ unsigned int        g_T32;
__device__ int                 g_cnt1, g_cnt2;
__device__ unsigned int        g_ctrd, g_ctrg;
__device__ int                 g_done;
__device__ unsigned long long  g_cand[2048];
__device__ unsigned long long  g_cand2[4096];
__device__ float4              g_cand_boxes[NPAD];
__device__ unsigned long long  g_mask[NPAD * NWORD];
__device__ float4              g_fboxes[KPOST];
__device__ int                 g_valid[KPOST];
__device__ float               g_featT[HW * CF];   // (H*W, C) ~41 MB

// ---------------- helpers ----------------
__device__ __forceinline__ unsigned flipf(float v) {
    unsigned u = __float_as_uint(v);
    return (u & 0x80000000u) ? ~u : (u | 0x80000000u);
}

// 64x64 transpose tile: f(C,H,W) -> g_featT(H*W, C)
__device__ __forceinline__ void transpose_tile(const float* __restrict__ f,
                                               int t, int tid, int nthr,
                                               float (*tile)[65]) {
    int pb = t % PT, cb = t / PT;
    int p0 = pb * 64, c0 = cb * 64;
    for (int i = tid; i < 64 * 64; i += nthr) {
        int ty = i >> 6, tx = i & 63;
        tile[ty][tx] = f[(size_t)(c0 + ty) * HW + p0 + tx];
    }
    __syncthreads();
    for (int i = tid; i < 64 * 64; i += nthr) {
        int pp = i >> 6, cc = i & 63;
        g_featT[(size_t)(p0 + pp) * CF + c0 + cc] = tile[cc][pp];
    }
}

// ---------------- K0: init ----------------
__global__ void init_kernel() {
    int g = blockIdx.x * 256 + threadIdx.x;
    if (g < 65536) g_hist[g] = 0u;
    else           g_hist2[g - 65536] = 0u;
    if (g == 0) { g_cnt1 = 0; g_cnt2 = 0; g_ctrd = 0; g_ctrg = 0; g_done = 0; }
}

// ---------------- K1: decode + histogram + (last block) coalesced threshold scan ----------------
__global__ void decode_kernel(const float4* __restrict__ anchors,
                              const float4* __restrict__ deltas,
                              const float*  __restrict__ obj, int N) {
    int i = blockIdx.x * 256 + threadIdx.x;
    if (i < N) {
        float4 a = anchors[i];
        float4 d = deltas[i];
        float w  = a.z - a.x, h = a.w - a.y;
        float cx = a.x + 0.5f * w, cy = a.y + 0.5f * h;
        float dw = fminf(d.z, CLIPC), dh = fminf(d.w, CLIPC);
        float pcx = d.x * w + cx, pcy = d.y * h + cy;
        float pw  = expf(dw) * w, ph = expf(dh) * h;
        float bx1 = fminf(fmaxf(pcx - 0.5f * pw, 0.f), IMG);
        float by1 = fminf(fmaxf(pcy - 0.5f * ph, 0.f), IMG);
        float bx2 = fminf(fmaxf(pcx + 0.5f * pw, 0.f), IMG);
        float by2 = fminf(fmaxf(pcy + 0.5f * ph, 0.f), IMG);
        ((float4*)g_boxes)[i] = make_float4(bx1, by1, bx2, by2);
        atomicAdd(&g_hist[flipf(obj[i]) >> 16], 1u);
    }
    __syncthreads();
    __shared__ int lastf;
    if (threadIdx.x == 0) {
        __threadfence();
        lastf = (atomicAdd(&g_ctrd, 1u) == gridDim.x - 1);
    }
    __syncthreads();
    if (!lastf) return;

    // last block: find 16-bit threshold (coalesced)
    __shared__ unsigned csum[256];
    __shared__ unsigned sbin[256];
    __shared__ int schunk;
    __shared__ unsigned sbase;
    int tid = threadIdx.x, w0 = tid >> 5, l = tid & 31;
    for (int t = w0; t < 256; t += 8) {
        unsigned s = 0;
        for (int b = l; b < 256; b += 32) s += g_hist[t * 256 + b];
        #pragma unroll
        for (int o = 16; o; o >>= 1) s += __shfl_down_sync(0xffffffffu, s, o);
        if (!l) csum[t] = s;
    }
    __syncthreads();
    if (tid == 0) {
        unsigned run = 0; int ch = 255; unsigned bs = 0;
        for (int t = 255; t >= 0; t--) {
            if (run + csum[t] >= KPRE) { ch = t; bs = run; break; }
            run += csum[t];
        }
        schunk = ch; sbase = bs;
    }
    __syncthreads();
    int ch = schunk;
    if (w0 == 0) for (int b = l; b < 256; b += 32) sbin[b] = g_hist[ch * 256 + b];
    __syncthreads();
    if (tid == 0) {
        unsigned cum = sbase;
        for (int b = 255; b >= 0; b--) {
            if (cum + sbin[b] >= KPRE) { g_T16 = ch * 256 + b; g_S = cum; break; }
            cum += sbin[b];
        }
    }
}

// ---------------- K2: gather candidates + (last block) 32-bit threshold refine ----------------
__global__ void gather_kernel(const float* __restrict__ obj, int N) {
    int i = blockIdx.x * 256 + threadIdx.x;
    if (i < N) {
        unsigned u = flipf(obj[i]);
        int hi = (int)(u >> 16);
        int T = g_T16;
        if (hi > T) {
            int p = atomicAdd(&g_cnt1, 1);
            if (p < 2048)
                g_cand[p] = ((unsigned long long)u << 32) |
                            (unsigned long long)(0xFFFFFFFFu - (unsigned)i);
        } else if (hi == T) {
            int p = atomicAdd(&g_cnt2, 1);
            if (p < 4096)
                g_cand2[p] = ((unsigned long long)u << 32) |
                             (unsigned long long)(0xFFFFFFFFu - (unsigned)i);
            atomicAdd(&g_hist2[u & 0xFFFFu], 1u);
        }
    }
    __syncthreads();
    __shared__ int lastf;
    if (threadIdx.x == 0) {
        __threadfence();
        lastf = (atomicAdd(&g_ctrg, 1u) == gridDim.x - 1);
    }
    __syncthreads();
    if (!lastf) return;

    __shared__ unsigned csum[256];
    __shared__ unsigned sbin[256];
    __shared__ int schunk;
    __shared__ unsigned sbase;
    int tid = threadIdx.x, w0 = tid >> 5, l = tid & 31;
    for (int t = w0; t < 256; t += 8) {
        unsigned s = 0;
        for (int b = l; b < 256; b += 32) s += g_hist2[t * 256 + b];
        #pragma unroll
        for (int o = 16; o; o >>= 1) s += __shfl_down_sync(0xffffffffu, s, o);
        if (!l) csum[t] = s;
    }
    __syncthreads();
    unsigned need = KPRE - g_S;
    if (tid == 0) {
        unsigned run = 0; int ch = 0; unsigned bs = 0;
        for (int t = 255; t >= 0; t--) {
            if (run + csum[t] >= need) { ch = t; bs = run; break; }
            run += csum[t];
        }
        schunk = ch; sbase = bs;
    }
    __syncthreads();
    int ch = schunk;
    if (w0 == 0) for (int b = l; b < 256; b += 32) sbin[b] = g_hist2[ch * 256 + b];
    __syncthreads();
    if (tid == 0) {
        unsigned cum = sbase;
        for (int b = 255; b >= 0; b--) {
            if (cum + sbin[b] >= need) {
                g_T32 = ((unsigned)g_T16 << 16) | (unsigned)(ch * 256 + b);
                break;
            }
            cum += sbin[b];
        }
    }
}

// ---------------- K3: block 0 sorts top-2048; other blocks transpose (half 1) ----------------
__global__ void sort_kernel(const float* __restrict__ f) {
    __shared__ unsigned long long sk[NPAD];   // 16 KB
    __shared__ float tile[64][65];            // 16.6 KB
    int tid = threadIdx.x;
    if (blockIdx.x != 0) {
        transpose_tile(f, blockIdx.x - 1, tid, 1024, tile);
        return;
    }
    __shared__ int scount;
    if (tid == 0) scount = 0;
    for (int idx = tid; idx < NPAD; idx += 1024) sk[idx] = 0ull;
    __syncthreads();
    unsigned T32 = g_T32;
    int n1 = g_cnt1; if (n1 > 2048) n1 = 2048;
    for (int k = tid; k < n1; k += 1024) {
        int pos = atomicAdd(&scount, 1);
        if (pos < NPAD) sk[pos] = g_cand[k];
    }
    int n2 = g_cnt2; if (n2 > 4096) n2 = 4096;
    for (int k = tid; k < n2; k += 1024) {
        unsigned long long key = g_cand2[k];
        if ((unsigned)(key >> 32) >= T32) {
            int pos = atomicAdd(&scount, 1);
            if (pos < NPAD) sk[pos] = key;
        }
    }
    __syncthreads();
    for (int k = 2; k <= NPAD; k <<= 1) {
        for (int j = k >> 1; j > 0; j >>= 1) {
            for (int idx = tid; idx < NPAD; idx += 1024) {
                int ixj = idx ^ j;
                if (ixj > idx) {
                    bool desc = ((idx & k) == 0);
                    unsigned long long a = sk[idx], c = sk[ixj];
                    if ((a < c) == desc) { sk[idx] = c; sk[ixj] = a; }
                }
            }
            __syncthreads();
        }
    }
    for (int t = tid; t < NPAD; t += 1024) {
        unsigned long long key = sk[t];
        if (t < KPRE && key != 0ull) {
            unsigned i = ~(unsigned)(key & 0xFFFFFFFFull);
            g_cand_boxes[t] = ((const float4*)g_boxes)[i];
        } else {
            g_cand_boxes[t] = make_float4(0.f, 0.f, 0.f, 0.f);
        }
    }
}

// ---------------- IoU tile body ----------------
__device__ __forceinline__ void iou_tile(int ib, int by, int tx) {
    __shared__ float4 cb[64];
    __shared__ float  cA[64];
    int i = ib * 64 + tx;
    int tid = threadIdx.x;
    if (tid < 64) {
        float4 b = g_cand_boxes[by * 64 + tid];
        cb[tid] = b;
        cA[tid] = 0.7f * (b.z - b.x) * (b.w - b.y);
    }
    __syncthreads();
    if (by < ib) { g_mask[(size_t)i * NWORD + by] = 0ull; return; }
    float4 a = g_cand_boxes[i];
    float c0 = 0.7f * ((a.z - a.x) * (a.w - a.y) + 1e-6f);
    unsigned long long bits = 0ull;
    #pragma unroll 8
    for (int jj = 0; jj < 64; jj++) {
        float4 b = cb[jj];
        float lx = fmaxf(a.x, b.x), ly = fmaxf(a.y, b.y);
        float rx = fminf(a.z, b.z), ry = fminf(a.w, b.w);
        float wx = fmaxf(rx - lx, 0.f), wy = fmaxf(ry - ly, 0.f);
        float inter = wx * wy;
        unsigned long long p = (fmaf(1.7f, inter, -(c0 + cA[jj])) > 0.f);
        bits |= p << jj;
    }
    if (by == ib) bits &= (tx == 63) ? 0ull : (~0ull << (tx + 1));
    g_mask[(size_t)i * NWORD + by] = bits;
}

// K4: IoU for top-left 1024x1024 only
__global__ void iou_top_kernel() {
    int ib = blockIdx.x * 4 + (threadIdx.x >> 6);   // 0..15
    int by = blockIdx.y;                            // 0..15
    iou_tile(ib, by, threadIdx.x & 63);
}

// K6: full IoU fallback (skipped when fast path succeeded)
__global__ void iou_full_kernel() {
    __shared__ int sdone;
    if (threadIdx.x == 0) sdone = g_done;
    __syncthreads();
    if (sdone) return;
    int ib = blockIdx.x * 4 + (threadIdx.x >> 6);   // 0..31
    int by = blockIdx.y;                            // 0..31
    if (ib < 16 && by < 16) return;                 // already computed
    iou_tile(ib, by, threadIdx.x & 63);
}

// ---------------- NMS scan + compaction ----------------
__device__ __forceinline__ void nms_compact_body(int nchunk, bool is_try) {
    int lane = threadIdx.x & 31;
    __shared__ unsigned long long diag[64];
    __shared__ unsigned long long skeep[NWORD];
    unsigned long long removed = 0ull;
    int kept_total = 0;
    int c = 0;
    for (; c < nchunk; c++) {
        unsigned long long keepmask = (c == NWORD - 1) ? 0xFFFFull : ~0ull;
        int base = c * 64;
        diag[lane]      = g_mask[(size_t)(base + lane)      * NWORD + c];
        diag[lane + 32] = g_mask[(size_t)(base + lane + 32) * NWORD + c];
        __syncwarp();
        unsigned long long cur  = __shfl_sync(0xffffffffu, removed, c);
        unsigned long long todo = ~cur & keepmask;
        unsigned long long kept = 0ull;
        while (todo) {
            int b = __ffsll((long long)todo) - 1;
            kept |= 1ull << b;
            unsigned long long d = diag[b];
            removed |= g_mask[(size_t)(base + b) * NWORD + lane];
            todo &= ~(d | (1ull << b));
        }
        if (lane == 0) skeep[c] = kept;
        kept_total += __popcll(kept);
        if (kept_total >= KPOST) { c++; break; }
    }
    if (is_try && kept_total < KPOST) return;   // fast path failed; full path will handle
    for (int cc = c + lane; cc < NWORD; cc += 32) skeep[cc] = 0ull;
    __syncwarp();
    for (int s = lane; s < KPOST; s += 32) g_valid[s] = 0;
    __syncwarp();
    unsigned long long kw = skeep[lane];
    int cnt = __popcll(kw);
    int pre = cnt;
    #pragma unroll
    for (int o = 1; o < 32; o <<= 1) {
        int n = __shfl_up_sync(0xffffffffu, pre, o);
        if (lane >= o) pre += n;
    }
    pre -= cnt;
    unsigned long long w = kw; int r = 0;
    while (w) {
        int b = __ffsll((long long)w) - 1;
        int s = pre + r;
        if (s < KPOST) {
            g_valid[s] = 1;
            g_fboxes[s] = g_cand_boxes[lane * 64 + b];
        }
        w &= (w - 1); r++;
    }
    if (lane == 0) g_done = 1;
}

// K5: early-exit NMS over first 1024 boxes; other blocks transpose (half 2)
__global__ void nms_try_kernel(const float* __restrict__ f) {
    __shared__ float tile[64][65];
    if (blockIdx.x != 0) {
        transpose_tile(f, THALF + blockIdx.x - 1, threadIdx.x, 256, tile);
        return;
    }
    if (threadIdx.x < 32) nms_compact_body(16, true);
}

// K7: full NMS fallback
__global__ void nms_full_kernel() {
    if (g_done) return;
    nms_compact_body(NWORD, false);
}

// ---------------- K8: ROIAlign ----------------
#define SOUT_F 12596
#define ROI_SMEM (SOUT_F*4 + 196*16 + 196*16)

__global__ void roi_kernel(float* __restrict__ out) {
    extern __shared__ float sm[];
    float*  s_out = sm;
    int4*   s_off = (int4*)(sm + SOUT_F);
    float4* s_w   = (float4*)(s_off + 196);

    int slot = blockIdx.x;
    int tid  = threadIdx.x;
    float* o = out + (size_t)slot * (CF * 49);

    if (!g_valid[slot]) {
        for (int g = tid; g < CF * 49; g += 256) o[g] = 0.0f;
        return;
    }
    float4 b = g_fboxes[slot];
    if (tid < 196) {
        float x1 = b.x * SCALE, y1 = b.y * SCALE;
        float x2 = b.z * SCALE, y2 = b.w * SCALE;
        float rw = fmaxf(x2 - x1, 1.0f), rh = fmaxf(y2 - y1, 1.0f);
        int sy = tid / 14, sx = tid % 14;
        float yv = y1 + ((float)sy + 0.5f) * (rh / 14.0f);
        float xv = x1 + ((float)sx + 0.5f) * (rw / 14.0f);
        yv = fminf(fmaxf(yv, 0.0f), (float)(HF - 1));
        xv = fminf(fmaxf(xv, 0.0f), (float)(WF - 1));
        int y0 = (int)floorf(yv), x0 = (int)floorf(xv);
        int y1i = min(y0 + 1, HF - 1), x1i = min(x0 + 1, WF - 1);
        float ly = yv - (float)y0, lx = xv - (float)x0;
        s_off[tid] = make_int4(y0 * WF + x0, y0 * WF + x1i,
                               y1i * WF + x0, y1i * WF + x1i);
        s_w[tid] = make_float4((1.f - ly) * (1.f - lx), (1.f - ly) * lx,
                               ly * (1.f - lx),          ly * lx);
    }
    __syncthreads();

    int cg = tid & 63;
    int pq = tid >> 6;
    const float4* ft = (const float4*)g_featT;

    for (int p = pq; p < 49; p += 4) {
        int oy = p / 7, ox = p % 7;
        float ax = 0.f, ay = 0.f, az = 0.f, aw = 0.f;
        #pragma unroll
        for (int a = 0; a < 2; a++) {
            #pragma unroll
            for (int bb = 0; bb < 2; bb++) {
                int s = (2 * oy + a) * 14 + (2 * ox + bb);
                int4   of = s_off[s];
                float4 wv = s_w[s];
                float4 f00 = ft[(size_t)of.x * 64 + cg];
                float4 f01 = ft[(size_t)of.y * 64 + cg];
                float4 f10 = ft[(size_t)of.z * 64 + cg];
                float4 f11 = ft[(size_t)of.w * 64 + cg];
                ax += wv.x * f00.x + wv.y * f01.x + wv.z * f10.x + wv.w * f11.x;
                ay += wv.x * f00.y + wv.y * f01.y + wv.z * f10.y + wv.w * f11.y;
                az += wv.x * f00.z + wv.y * f01.z + wv.z * f10.z + wv.w * f11.z;
                aw += wv.x * f00.w + wv.y * f01.w + wv.z * f10.w + wv.w * f11.w;
            }
        }
        int base = p * 257 + 4 * cg;
        s_out[base + 0] = ax * 0.25f;
        s_out[base + 1] = ay * 0.25f;
        s_out[base + 2] = az * 0.25f;
        s_out[base + 3] = aw * 0.25f;
    }
    __syncthreads();

    for (int g = tid; g < CF * 49; g += 256) {
        int cc = g / 49;
        int p  = g - 49 * cc;
        o[g] = s_out[p * 257 + cc];
    }
}

// ---------------- launcher ----------------
extern "C" void kernel_launch(void* const* d_in, const int* in_sizes, int n_in,
                              void* d_out, int out_size) {
    const float*  feature = (const float*)d_in[0];
    const float*  obj     = (const float*)d_in[1];
    const float4* deltas  = (const float4*)d_in[2];
    const float4* anchors = (const float4*)d_in[3];
    float* out = (float*)d_out;
    int N = in_sizes[1];
    int nb = (N + 255) / 256;

    cudaFuncSetAttribute(roi_kernel, cudaFuncAttributeMaxDynamicSharedMemorySize, ROI_SMEM);

    init_kernel<<<512, 256>>>();
    decode_kernel<<<nb, 256>>>(anchors, deltas, obj, N);
    gather_kernel<<<nb, 256>>>(obj, N);
    sort_kernel<<<1 + THALF, 1024>>>(feature);
    iou_top_kernel<<<dim3(4, 16), 256>>>();
    nms_try_kernel<<<1 + THALF, 256>>>(feature);
    iou_full_kernel<<<dim3(8, 32), 256>>>();
    nms_full_kernel<<<1, 32>>>();
    roi_kernel<<<KPOST, 256, ROI_SMEM>>>(out);
}

// round 4
// speedup vs baseline: 1.3341x; 1.3341x over previous
#include <cuda_runtime.h>
#include <cuda_fp16.h>
#include <math.h>

// ---------------- problem constants ----------------
#define NANCH   120000
#define KPRE    2000
#define KPOST   512
#define IMG     800.0f
#define SCALE   0.25f
#define CLIPC   4.135166556742356f
#define HF      200
#define WF      200
#define CF      256
#define HW      (HF*WF)          // 40000
#define NWORD   32
#define NPAD    2048
#define PT      625              // 64-wide p tiles
#define CT      4                // 64-wide c tiles
#define TTOT    (PT*CT)          // 2500
#define NTRI    528              // upper-tri 64x64 IoU tiles (32*33/2)

// ---------------- device scratch ----------------
__device__ float               g_boxes[NANCH * 4];
__device__ unsigned int        g_hist[65536];
__device__ unsigned int        g_hist2[65536];
__device__ int                 g_T16;
__device__ unsigned int        g_S;
__device__ unsigned int        g_T32;
__device__ int                 g_cnt1, g_cnt2;
__device__ unsigned int        g_ctrd, g_ctrg, g_ctri;
__device__ unsigned long long  g_cand[2048];
__device__ unsigned long long  g_cand2[4096];
__device__ float4              g_cand_boxes[NPAD];
__device__ unsigned long long  g_mask[NPAD * NWORD];   // only upper-tri written; .bss zeros elsewhere
__device__ float4              g_fboxes[KPOST];
__device__ int                 g_valid[KPOST];
__device__ __align__(16) __half g_featT[HW * CF];      // (H*W, C) fp16, ~20.5 MB

// ---------------- helpers ----------------
__device__ __forceinline__ unsigned flipf(float v) {
    unsigned u = __float_as_uint(v);
    return (u & 0x80000000u) ? ~u : (u | 0x80000000u);
}

// ---------------- K0: init ----------------
__global__ void init_kernel() {
    int g = blockIdx.x * 256 + threadIdx.x;
    if (g < 65536) g_hist[g] = 0u;
    else           g_hist2[g - 65536] = 0u;
    if (g == 0) { g_cnt1 = 0; g_cnt2 = 0; g_ctrd = 0; g_ctrg = 0; g_ctri = 0; }
}

// ---------------- K1: decode + histogram + (last block) coalesced 16-bit scan ----------------
__global__ void decode_kernel(const float4* __restrict__ anchors,
                              const float4* __restrict__ deltas,
                              const float*  __restrict__ obj, int N) {
    int i = blockIdx.x * 256 + threadIdx.x;
    if (i < N) {
        float4 a = anchors[i];
        float4 d = deltas[i];
        float w  = a.z - a.x, h = a.w - a.y;
        float cx = a.x + 0.5f * w, cy = a.y + 0.5f * h;
        float dw = fminf(d.z, CLIPC), dh = fminf(d.w, CLIPC);
        float pcx = d.x * w + cx, pcy = d.y * h + cy;
        float pw  = expf(dw) * w, ph = expf(dh) * h;
        float bx1 = fminf(fmaxf(pcx - 0.5f * pw, 0.f), IMG);
        float by1 = fminf(fmaxf(pcy - 0.5f * ph, 0.f), IMG);
        float bx2 = fminf(fmaxf(pcx + 0.5f * pw, 0.f), IMG);
        float by2 = fminf(fmaxf(pcy + 0.5f * ph, 0.f), IMG);
        ((float4*)g_boxes)[i] = make_float4(bx1, by1, bx2, by2);
        atomicAdd(&g_hist[flipf(obj[i]) >> 16], 1u);
    }
    __syncthreads();
    __shared__ int lastf;
    if (threadIdx.x == 0) {
        __threadfence();
        lastf = (atomicAdd(&g_ctrd, 1u) == gridDim.x - 1);
    }
    __syncthreads();
    if (!lastf) return;

    __shared__ unsigned csum[256];
    __shared__ unsigned sbin[256];
    __shared__ int schunk;
    __shared__ unsigned sbase;
    int tid = threadIdx.x, w0 = tid >> 5, l = tid & 31;
    for (int t = w0; t < 256; t += 8) {
        unsigned s = 0;
        for (int b = l; b < 256; b += 32) s += g_hist[t * 256 + b];
        #pragma unroll
        for (int o = 16; o; o >>= 1) s += __shfl_down_sync(0xffffffffu, s, o);
        if (!l) csum[t] = s;
    }
    __syncthreads();
    if (tid == 0) {
        unsigned run = 0; int ch = 255; unsigned bs = 0;
        for (int t = 255; t >= 0; t--) {
            if (run + csum[t] >= KPRE) { ch = t; bs = run; break; }
            run += csum[t];
        }
        schunk = ch; sbase = bs;
    }
    __syncthreads();
    int ch = schunk;
    if (w0 == 0) for (int b = l; b < 256; b += 32) sbin[b] = g_hist[ch * 256 + b];
    __syncthreads();
    if (tid == 0) {
        unsigned cum = sbase;
        for (int b = 255; b >= 0; b--) {
            if (cum + sbin[b] >= KPRE) { g_T16 = ch * 256 + b; g_S = cum; break; }
            cum += sbin[b];
        }
    }
}

// ---------------- K2: gather + (last block) 32-bit refine ----------------
__global__ void gather_kernel(const float* __restrict__ obj, int N) {
    int i = blockIdx.x * 256 + threadIdx.x;
    if (i < N) {
        unsigned u = flipf(obj[i]);
        int hi = (int)(u >> 16);
        int T = g_T16;
        if (hi > T) {
            int p = atomicAdd(&g_cnt1, 1);
            if (p < 2048)
                g_cand[p] = ((unsigned long long)u << 32) |
                            (unsigned long long)(0xFFFFFFFFu - (unsigned)i);
        } else if (hi == T) {
            int p = atomicAdd(&g_cnt2, 1);
            if (p < 4096)
                g_cand2[p] = ((unsigned long long)u << 32) |
                             (unsigned long long)(0xFFFFFFFFu - (unsigned)i);
            atomicAdd(&g_hist2[u & 0xFFFFu], 1u);
        }
    }
    __syncthreads();
    __shared__ int lastf;
    if (threadIdx.x == 0) {
        __threadfence();
        lastf = (atomicAdd(&g_ctrg, 1u) == gridDim.x - 1);
    }
    __syncthreads();
    if (!lastf) return;

    __shared__ unsigned csum[256];
    __shared__ unsigned sbin[256];
    __shared__ int schunk;
    __shared__ unsigned sbase;
    int tid = threadIdx.x, w0 = tid >> 5, l = tid & 31;
    for (int t = w0; t < 256; t += 8) {
        unsigned s = 0;
        for (int b = l; b < 256; b += 32) s += g_hist2[t * 256 + b];
        #pragma unroll
        for (int o = 16; o; o >>= 1) s += __shfl_down_sync(0xffffffffu, s, o);
        if (!l) csum[t] = s;
    }
    __syncthreads();
    unsigned need = KPRE - g_S;
    if (tid == 0) {
        unsigned run = 0; int ch = 0; unsigned bs = 0;
        for (int t = 255; t >= 0; t--) {
            if (run + csum[t] >= need) { ch = t; bs = run; break; }
            run += csum[t];
        }
        schunk = ch; sbase = bs;
    }
    __syncthreads();
    int ch = schunk;
    if (w0 == 0) for (int b = l; b < 256; b += 32) sbin[b] = g_hist2[ch * 256 + b];
    __syncthreads();
    if (tid == 0) {
        unsigned cum = sbase;
        for (int b = 255; b >= 0; b--) {
            if (cum + sbin[b] >= need) {
                g_T32 = ((unsigned)g_T16 << 16) | (unsigned)(ch * 256 + b);
                break;
            }
            cum += sbin[b];
        }
    }
}

// ---------------- K3: block 0 = bitonic sort-2048; blocks 1.. = fp16 transpose ----------------
__global__ void sort_transpose_kernel(const float* __restrict__ f) {
    __shared__ float tile[64][65];            // 16.6 KB
    __shared__ unsigned long long sk[NPAD];   // 16 KB
    int tid = threadIdx.x;
    if (blockIdx.x != 0) {
        int t  = blockIdx.x - 1;              // 0..2499
        int pb = t % PT, cb = t / PT;
        int p0 = pb * 64, c0 = cb * 64;
        int ty = tid >> 4, tx = tid & 15;
        float4 v = *(const float4*)&f[(size_t)(c0 + ty) * HW + p0 + 4 * tx];
        tile[ty][4 * tx + 0] = v.x;
        tile[ty][4 * tx + 1] = v.y;
        tile[ty][4 * tx + 2] = v.z;
        tile[ty][4 * tx + 3] = v.w;
        __syncthreads();
        int pp = tid >> 4, k = tid & 15;
        float a = tile[4 * k + 0][pp];
        float b = tile[4 * k + 1][pp];
        float c = tile[4 * k + 2][pp];
        float d = tile[4 * k + 3][pp];
        __half2 h0 = __floats2half2_rn(a, b);
        __half2 h1 = __floats2half2_rn(c, d);
        uint2 pk;
        pk.x = *(unsigned*)&h0;
        pk.y = *(unsigned*)&h1;
        *(uint2*)&g_featT[(size_t)(p0 + pp) * CF + c0 + 4 * k] = pk;
        return;
    }
    __shared__ int scount;
    if (tid == 0) scount = 0;
    for (int idx = tid; idx < NPAD; idx += 1024) sk[idx] = 0ull;
    __syncthreads();
    unsigned T32 = g_T32;
    int n1 = g_cnt1; if (n1 > 2048) n1 = 2048;
    for (int k = tid; k < n1; k += 1024) {
        int pos = atomicAdd(&scount, 1);
        if (pos < NPAD) sk[pos] = g_cand[k];
    }
    int n2 = g_cnt2; if (n2 > 4096) n2 = 4096;
    for (int k = tid; k < n2; k += 1024) {
        unsigned long long key = g_cand2[k];
        if ((unsigned)(key >> 32) >= T32) {
            int pos = atomicAdd(&scount, 1);
            if (pos < NPAD) sk[pos] = key;
        }
    }
    __syncthreads();
    for (int k = 2; k <= NPAD; k <<= 1) {
        for (int j = k >> 1; j > 0; j >>= 1) {
            for (int idx = tid; idx < NPAD; idx += 1024) {
                int ixj = idx ^ j;
                if (ixj > idx) {
                    bool desc = ((idx & k) == 0);
                    unsigned long long a = sk[idx], c = sk[ixj];
                    if ((a < c) == desc) { sk[idx] = c; sk[ixj] = a; }
                }
            }
            __syncthreads();
        }
    }
    for (int t = tid; t < NPAD; t += 1024) {
        unsigned long long key = sk[t];
        if (t < KPRE && key != 0ull) {
            unsigned i = ~(unsigned)(key & 0xFFFFFFFFull);
            g_cand_boxes[t] = ((const float4*)g_boxes)[i];
        } else {
            g_cand_boxes[t] = make_float4(0.f, 0.f, 0.f, 0.f);
        }
    }
}

// ---------------- NMS scan + compaction (one warp) ----------------
__device__ __forceinline__ void nms_compact_body() {
    int lane = threadIdx.x & 31;
    __shared__ unsigned long long diag[64];
    __shared__ unsigned long long skeep[NWORD];
    unsigned long long removed = 0ull;
    int kept_total = 0;
    int c = 0;
    for (; c < NWORD; c++) {
        unsigned long long keepmask = (c == NWORD - 1) ? 0xFFFFull : ~0ull;
        int base = c * 64;
        diag[lane]      = g_mask[(size_t)(base + lane)      * NWORD + c];
        diag[lane + 32] = g_mask[(size_t)(base + lane + 32) * NWORD + c];
        __syncwarp();
        unsigned long long cur  = __shfl_sync(0xffffffffu, removed, c);
        unsigned long long todo = ~cur & keepmask;
        unsigned long long kept = 0ull;
        while (todo) {
            int b = __ffsll((long long)todo) - 1;
            kept |= 1ull << b;
            unsigned long long d = diag[b];
            removed |= g_mask[(size_t)(base + b) * NWORD + lane];
            todo &= ~(d | (1ull << b));
        }
        if (lane == 0) skeep[c] = kept;
        kept_total += __popcll(kept);
        if (kept_total >= KPOST) { c++; break; }
    }
    for (int cc = c + lane; cc < NWORD; cc += 32) skeep[cc] = 0ull;
    __syncwarp();
    for (int s = lane; s < KPOST; s += 32) g_valid[s] = 0;
    __syncwarp();
    unsigned long long kw = skeep[lane];
    int cnt = __popcll(kw);
    int pre = cnt;
    #pragma unroll
    for (int o = 1; o < 32; o <<= 1) {
        int n = __shfl_up_sync(0xffffffffu, pre, o);
        if (lane >= o) pre += n;
    }
    pre -= cnt;
    unsigned long long w = kw; int r = 0;
    while (w) {
        int b = __ffsll((long long)w) - 1;
        int s = pre + r;
        if (s < KPOST) {
            g_valid[s] = 1;
            g_fboxes[s] = g_cand_boxes[lane * 64 + b];
        }
        w &= (w - 1); r++;
    }
}

// ---------------- K4: upper-tri IoU tiles + (last block) NMS tail ----------------
__global__ void iou_nms_kernel() {
    __shared__ float4 cb[4][64];
    __shared__ float  cA[4][64];
    int tid = threadIdx.x;
    int sub = tid >> 6, tx = tid & 63;
    int t = blockIdx.x * 4 + sub;             // 0..527

    // triangular decode: t -> (ib, by), ib <= by
    int ib = 0, off = 0;
    for (int r = 0; r < 32; r++) {
        int cnt = 32 - r;
        if (t < off + cnt) { ib = r; break; }
        off += cnt;
    }
    int by = ib + (t - off);

    float4 bb = g_cand_boxes[by * 64 + tx];
    cb[sub][tx] = bb;
    cA[sub][tx] = 0.7f * (bb.z - bb.x) * (bb.w - bb.y);
    __syncthreads();

    int i = ib * 64 + tx;
    float4 a = g_cand_boxes[i];
    float c0 = 0.7f * ((a.z - a.x) * (a.w - a.y) + 1e-6f);
    unsigned long long bits = 0ull;
    #pragma unroll 8
    for (int jj = 0; jj < 64; jj++) {
        float4 b = cb[sub][jj];
        float lx = fmaxf(a.x, b.x), ly = fmaxf(a.y, b.y);
        float rx = fminf(a.z, b.z), ry = fminf(a.w, b.w);
        float wx = fmaxf(rx - lx, 0.f), wy = fmaxf(ry - ly, 0.f);
        float inter = wx * wy;
        unsigned long long p = (fmaf(1.7f, inter, -(c0 + cA[sub][jj])) > 0.f);
        bits |= p << jj;
    }
    if (by == ib) bits &= (tx == 63) ? 0ull : (~0ull << (tx + 1));
    g_mask[(size_t)i * NWORD + by] = bits;

    // last-arriving block runs the sequential NMS + compaction
    __syncthreads();
    __shared__ int lastf;
    if (tid == 0) {
        __threadfence();
        lastf = (atomicAdd(&g_ctri, 1u) == gridDim.x - 1);
    }
    __syncthreads();
    if (lastf && tid < 32) nms_compact_body();
}

// ---------------- K5: ROIAlign (fp16 channels-last, smem-staged output) ----------------
#define SOUT_F 12596
#define ROI_SMEM (SOUT_F*4 + 196*16 + 196*16)

__global__ void roi_kernel(float* __restrict__ out) {
    extern __shared__ float sm[];
    float*  s_out = sm;
    int4*   s_off = (int4*)(sm + SOUT_F);
    float4* s_w   = (float4*)(s_off + 196);

    int slot = blockIdx.x;
    int tid  = threadIdx.x;
    float* o = out + (size_t)slot * (CF * 49);

    if (!g_valid[slot]) {
        for (int g = tid; g < CF * 49; g += 256) o[g] = 0.0f;
        return;
    }
    float4 b = g_fboxes[slot];
    if (tid < 196) {
        float x1 = b.x * SCALE, y1 = b.y * SCALE;
        float x2 = b.z * SCALE, y2 = b.w * SCALE;
        float rw = fmaxf(x2 - x1, 1.0f), rh = fmaxf(y2 - y1, 1.0f);
        int sy = tid / 14, sx = tid % 14;
        float yv = y1 + ((float)sy + 0.5f) * (rh / 14.0f);
        float xv = x1 + ((float)sx + 0.5f) * (rw / 14.0f);
        yv = fminf(fmaxf(yv, 0.0f), (float)(HF - 1));
        xv = fminf(fmaxf(xv, 0.0f), (float)(WF - 1));
        int y0 = (int)floorf(yv), x0 = (int)floorf(xv);
        int y1i = min(y0 + 1, HF - 1), x1i = min(x0 + 1, WF - 1);
        float ly = yv - (float)y0, lx = xv - (float)x0;
        s_off[tid] = make_int4(y0 * WF + x0, y0 * WF + x1i,
                               y1i * WF + x0, y1i * WF + x1i);
        s_w[tid] = make_float4((1.f - ly) * (1.f - lx), (1.f - ly) * lx,
                               ly * (1.f - lx),          ly * lx);
    }
    __syncthreads();

    int cg = tid & 63;   // channels 4cg..4cg+3
    int pq = tid >> 6;

    for (int p = pq; p < 49; p += 4) {
        int oy = p / 7, ox = p % 7;
        float ax = 0.f, ay = 0.f, az = 0.f, aw = 0.f;
        #pragma unroll
        for (int a = 0; a < 2; a++) {
            #pragma unroll
            for (int bbq = 0; bbq < 2; bbq++) {
                int s = (2 * oy + a) * 14 + (2 * ox + bbq);
                int4   of = s_off[s];
                float4 wv = s_w[s];
                uint2 r00 = *(const uint2*)&g_featT[(size_t)of.x * CF + 4 * cg];
                uint2 r01 = *(const uint2*)&g_featT[(size_t)of.y * CF + 4 * cg];
                uint2 r10 = *(const uint2*)&g_featT[(size_t)of.z * CF + 4 * cg];
                uint2 r11 = *(const uint2*)&g_featT[(size_t)of.w * CF + 4 * cg];
                float2 a0 = __half22float2(*(__half2*)&r00.x);
                float2 a1 = __half22float2(*(__half2*)&r00.y);
                float2 b0 = __half22float2(*(__half2*)&r01.x);
                float2 b1 = __half22float2(*(__half2*)&r01.y);
                float2 c0 = __half22float2(*(__half2*)&r10.x);
                float2 c1 = __half22float2(*(__half2*)&r10.y);
                float2 d0 = __half22float2(*(__half2*)&r11.x);
                float2 d1 = __half22float2(*(__half2*)&r11.y);
                ax += wv.x * a0.x + wv.y * b0.x + wv.z * c0.x + wv.w * d0.x;
                ay += wv.x * a0.y + wv.y * b0.y + wv.z * c0.y + wv.w * d0.y;
                az += wv.x * a1.x + wv.y * b1.x + wv.z * c1.x + wv.w * d1.x;
                aw += wv.x * a1.y + wv.y * b1.y + wv.z * c1.y + wv.w * d1.y;
            }
        }
        int base = p * 257 + 4 * cg;
        s_out[base + 0] = ax * 0.25f;
        s_out[base + 1] = ay * 0.25f;
        s_out[base + 2] = az * 0.25f;
        s_out[base + 3] = aw * 0.25f;
    }
    __syncthreads();

    for (int g = tid; g < CF * 49; g += 256) {
        int cc = g / 49;
        int p  = g - 49 * cc;
        o[g] = s_out[p * 257 + cc];
    }
}

// ---------------- launcher ----------------
extern "C" void kernel_launch(void* const* d_in, const int* in_sizes, int n_in,
                              void* d_out, int out_size) {
    const float*  feature = (const float*)d_in[0];
    const float*  obj     = (const float*)d_in[1];
    const float4* deltas  = (const float4*)d_in[2];
    const float4* anchors = (const float4*)d_in[3];
    float* out = (float*)d_out;
    int N = in_sizes[1];
    int nb = (N + 255) / 256;

    cudaFuncSetAttribute(roi_kernel, cudaFuncAttributeMaxDynamicSharedMemorySize, ROI_SMEM);

    init_kernel<<<512, 256>>>();
    decode_kernel<<<nb, 256>>>(anchors, deltas, obj, N);
    gather_kernel<<<nb, 256>>>(obj, N);
    sort_transpose_kernel<<<1 + TTOT, 1024>>>(feature);
    iou_nms_kernel<<<NTRI / 4, 256>>>();
    roi_kernel<<<KPOST, 256, ROI_SMEM>>>(out);
}